// round 8
// baseline (speedup 1.0000x reference)
#include <cuda_runtime.h>
#include <math.h>
#include <cstdint>

#define DIM 768
#define HEADS 12
#define HEAD_DIM 64
#define BATCH 4
#define SEQ 2048
#define QKV_DIM (3 * DIM)
#define QSCALE 0.18033688011112042f  /* 0.125 * log2(e) */

__device__ float g_qkv[(size_t)BATCH * SEQ * QKV_DIM];
__device__ float g_att[(size_t)BATCH * SEQ * DIM];

__device__ __forceinline__ unsigned f2tf32(float x) {
    unsigned u;
    asm("cvt.rna.tf32.f32 %0, %1;" : "=r"(u) : "f"(x));
    return u;
}
__device__ __forceinline__ float ex2(float x) {
    float y;
    asm("ex2.approx.f32 %0, %1;" : "=f"(y) : "f"(x));
    return y;
}
__device__ __forceinline__ void mma_tf32(float c[4], const unsigned a[4],
                                         unsigned b0, unsigned b1) {
    asm volatile(
        "mma.sync.aligned.m16n8k8.row.col.f32.tf32.tf32.f32 "
        "{%0,%1,%2,%3}, {%4,%5,%6,%7}, {%8,%9}, {%0,%1,%2,%3};"
        : "+f"(c[0]), "+f"(c[1]), "+f"(c[2]), "+f"(c[3])
        : "r"(a[0]), "r"(a[1]), "r"(a[2]), "r"(a[3]), "r"(b0), "r"(b1));
}

// ===========================================================================
// TF32 GEMM (NT) v5: C = A[M,K]*B[N,K]^T + bias. 128x128 tile, BK=16,
// 256 threads = 8 warps (2m x 4n), warp tile 64x32 (mt=4, nt=4).
// Pair-packed smem (LDS.64 fragments), double-buffered, 1 sync per k-tile.
// __launch_bounds__(256,2) -> <=128 regs -> 2 CTAs/SM = 16 warps.
// ===========================================================================
#define GSA 136                      // A smem k-row stride (words)
#define GSB 40                       // B smem n-row stride (words)
#define G_ASIZE (16 * GSA)           // 2176 words
#define G_BSIZE (128 * GSB)          // 5120 words
#define G_BUF (G_ASIZE + G_BSIZE)    // 7296 words per buffer

extern __shared__ unsigned dyn_smem[];

__global__ __launch_bounds__(256, 2) void gemm_tf32_v5(
    const float* __restrict__ A, const float* __restrict__ B,
    const float* __restrict__ bias, float* __restrict__ C,
    int M, int N, int K) {
    const int tid = threadIdx.x;
    const int lane = tid & 31;
    const int wid = tid >> 5;
    const int wm = wid & 1, wn = wid >> 1;   // 2 x 4 warp grid
    const int bx = blockIdx.x, by = blockIdx.y;
    const int r0 = lane >> 2, q4 = lane & 3;

    // ---- loader mapping ----
    const bool isA = (tid < 128);
    // A loader (threads 0..127): pair-row (m, m+8), 8 k-values
    const int ap = (tid & 127) >> 1;          // 0..63 pair index
    const int ag = ap >> 3, ar = ap & 7;      // m = ag*16+ar (and +8)
    const int ak = (tid & 1) * 8;             // k offset 0 or 8
    // B loader (threads 128..255): row n = tid-128, all 16 k
    const float* gptr = isA
        ? A + (size_t)(by * 128 + ag * 16 + ar) * K + ak
        : B + (size_t)(bx * 128 + (tid - 128)) * K;
    const size_t gstep2 = (size_t)8 * K;      // A: partner row offset

    float st[16];
    {
        if (isA) {
            float4 a0 = *(const float4*)gptr;
            float4 a1 = *(const float4*)(gptr + 4);
            float4 b0 = *(const float4*)(gptr + gstep2);
            float4 b1 = *(const float4*)(gptr + gstep2 + 4);
            st[0] = a0.x; st[1] = a0.y; st[2] = a0.z; st[3] = a0.w;
            st[4] = a1.x; st[5] = a1.y; st[6] = a1.z; st[7] = a1.w;
            st[8] = b0.x; st[9] = b0.y; st[10] = b0.z; st[11] = b0.w;
            st[12] = b1.x; st[13] = b1.y; st[14] = b1.z; st[15] = b1.w;
        } else {
            float4 a0 = *(const float4*)gptr;
            float4 a1 = *(const float4*)(gptr + 4);
            float4 b0 = *(const float4*)(gptr + 8);
            float4 b1 = *(const float4*)(gptr + 12);
            st[0] = a0.x; st[1] = a0.y; st[2] = a0.z; st[3] = a0.w;
            st[4] = a1.x; st[5] = a1.y; st[6] = a1.z; st[7] = a1.w;
            st[8] = b0.x; st[9] = b0.y; st[10] = b0.z; st[11] = b0.w;
            st[12] = b1.x; st[13] = b1.y; st[14] = b1.z; st[15] = b1.w;
        }
    }

    float acc[4][4][4];
#pragma unroll
    for (int i = 0; i < 4; i++)
#pragma unroll
        for (int j = 0; j < 4; j++)
#pragma unroll
            for (int e = 0; e < 4; e++) acc[i][j][e] = 0.f;

    auto store_tile = [&](unsigned* s) {
        if (isA) {
            unsigned* As = s;
            const int jA = ag * 16 + ar * 2;
#pragma unroll
            for (int i = 0; i < 8; i++) {
                uint2 t;
                t.x = f2tf32(st[i]);
                t.y = f2tf32(st[8 + i]);
                *(uint2*)&As[(ak + i) * GSA + jA] = t;
            }
        } else {
            unsigned* Bs = s + G_ASIZE;
            const int n = tid - 128;
#pragma unroll
            for (int kb = 0; kb < 2; kb++)
#pragma unroll
                for (int qq = 0; qq < 4; qq++) {
                    uint2 t;
                    t.x = f2tf32(st[kb * 8 + qq]);
                    t.y = f2tf32(st[kb * 8 + qq + 4]);
                    *(uint2*)&Bs[n * GSB + kb * 8 + qq * 2] = t;
                }
        }
    };

    store_tile(dyn_smem);
    __syncthreads();

    const int NT = K / 16;
    for (int t = 0; t < NT; t++) {
        if (t + 1 < NT) {
            gptr += 16;
            if (isA) {
                float4 a0 = *(const float4*)gptr;
                float4 a1 = *(const float4*)(gptr + 4);
                float4 b0 = *(const float4*)(gptr + gstep2);
                float4 b1 = *(const float4*)(gptr + gstep2 + 4);
                st[0] = a0.x; st[1] = a0.y; st[2] = a0.z; st[3] = a0.w;
                st[4] = a1.x; st[5] = a1.y; st[6] = a1.z; st[7] = a1.w;
                st[8] = b0.x; st[9] = b0.y; st[10] = b0.z; st[11] = b0.w;
                st[12] = b1.x; st[13] = b1.y; st[14] = b1.z; st[15] = b1.w;
            } else {
                float4 a0 = *(const float4*)gptr;
                float4 a1 = *(const float4*)(gptr + 4);
                float4 b0 = *(const float4*)(gptr + 8);
                float4 b1 = *(const float4*)(gptr + 12);
                st[0] = a0.x; st[1] = a0.y; st[2] = a0.z; st[3] = a0.w;
                st[4] = a1.x; st[5] = a1.y; st[6] = a1.z; st[7] = a1.w;
                st[8] = b0.x; st[9] = b0.y; st[10] = b0.z; st[11] = b0.w;
                st[12] = b1.x; st[13] = b1.y; st[14] = b1.z; st[15] = b1.w;
            }
        }
        {
            const unsigned* As = dyn_smem + (t & 1) * G_BUF;
            const unsigned* Bs = As + G_ASIZE;
#pragma unroll
            for (int kc = 0; kc < 2; kc++) {
                const int kr = kc * 8 + q4;
                unsigned af[4][4];
#pragma unroll
                for (int mt = 0; mt < 4; mt++) {
                    const int j = (wm * 4 + mt) * 16 + r0 * 2;
                    uint2 p0 = *(const uint2*)&As[kr * GSA + j];
                    uint2 p1 = *(const uint2*)&As[(kr + 4) * GSA + j];
                    af[mt][0] = p0.x; af[mt][1] = p0.y;
                    af[mt][2] = p1.x; af[mt][3] = p1.y;
                }
#pragma unroll
                for (int nt = 0; nt < 4; nt++) {
                    const int n = wn * 32 + nt * 8 + r0;
                    uint2 bb = *(const uint2*)&Bs[n * GSB + kc * 8 + q4 * 2];
#pragma unroll
                    for (int mt = 0; mt < 4; mt++)
                        mma_tf32(acc[mt][nt], af[mt], bb.x, bb.y);
                }
            }
        }
        if (t + 1 < NT) store_tile(dyn_smem + ((t + 1) & 1) * G_BUF);
        __syncthreads();
    }

    // epilogue
#pragma unroll
    for (int nt = 0; nt < 4; nt++) {
        const int col = bx * 128 + wn * 32 + nt * 8 + 2 * q4;
        const float bv0 = __ldg(&bias[col]);
        const float bv1 = __ldg(&bias[col + 1]);
#pragma unroll
        for (int mt = 0; mt < 4; mt++) {
            const int row = by * 128 + wm * 64 + mt * 16 + r0;
            *(float2*)&C[(size_t)row * N + col] =
                make_float2(acc[mt][nt][0] + bv0, acc[mt][nt][1] + bv1);
            *(float2*)&C[(size_t)(row + 8) * N + col] =
                make_float2(acc[mt][nt][2] + bv0, acc[mt][nt][3] + bv1);
        }
    }
}

// ===========================================================================
// TF32 flash attention v4: identical to v3 except the S=Q*K^T loop is
// reordered (kc outer, nc inner) so the 16 accumulators form independent
// dependency chains instead of distance-2 RAW chains on the tensor pipe.
// ===========================================================================
#define KS 72
#define PS 136
#define F_V (64 * KS)
#define F_P (2 * 64 * KS)
#define F_WORDS (F_P + 8 * 8 * PS)

__global__ __launch_bounds__(128) void flash_tf32_v4(
    const float* __restrict__ qkv, float* __restrict__ out) {
    unsigned* ks2 = dyn_smem;
    unsigned* vp = dyn_smem + F_V;

    const int tid = threadIdx.x;
    const int lane = tid & 31;
    const int wid = tid >> 5;
    const int r0 = lane >> 2, q4 = lane & 3;
    const int qt = blockIdx.x, h = blockIdx.y, b = blockIdx.z;
    unsigned* pw = dyn_smem + F_P + wid * (2 * 8 * PS);

    const size_t base = (size_t)b * SEQ * QKV_DIM;

    unsigned qa[2][8][4];
#pragma unroll
    for (int mt = 0; mt < 2; mt++) {
        const int row = qt * 128 + wid * 32 + mt * 16 + r0;
        const float* p0 = qkv + base + (size_t)row * QKV_DIM + h * HEAD_DIM + q4;
        const float* p1 = p0 + (size_t)8 * QKV_DIM;
#pragma unroll
        for (int kc = 0; kc < 8; kc++) {
            qa[mt][kc][0] = f2tf32(p0[kc * 8] * QSCALE);
            qa[mt][kc][1] = f2tf32(p1[kc * 8] * QSCALE);
            qa[mt][kc][2] = f2tf32(p0[kc * 8 + 4] * QSCALE);
            qa[mt][kc][3] = f2tf32(p1[kc * 8 + 4] * QSCALE);
        }
    }

    float o[2][8][4];
#pragma unroll
    for (int mt = 0; mt < 2; mt++)
#pragma unroll
        for (int nc = 0; nc < 8; nc++)
#pragma unroll
            for (int e = 0; e < 4; e++) o[mt][nc][e] = 0.f;
    float mA[2] = {-1e30f, -1e30f}, mB[2] = {-1e30f, -1e30f};
    float lA[2] = {0.f, 0.f}, lB[2] = {0.f, 0.f};

    const int kkey = tid >> 1;
    const int kc0 = (tid & 1) * 32;
    const int vpr = tid >> 2;
    const int vkb = vpr >> 2, vq = vpr & 3;
    const int vr0 = vkb * 8 + vq;
    const int vcs = (tid & 3) * 16;

    for (int kt = 0; kt < SEQ / 64; kt++) {
        {
            const float* kg = qkv + base + (size_t)(kt * 64 + kkey) * QKV_DIM
                              + DIM + h * HEAD_DIM + kc0;
            float kf[32];
#pragma unroll
            for (int i = 0; i < 8; i++) {
                float4 t = *(const float4*)(kg + i * 4);
                kf[i * 4 + 0] = t.x; kf[i * 4 + 1] = t.y;
                kf[i * 4 + 2] = t.z; kf[i * 4 + 3] = t.w;
            }
#pragma unroll
            for (int kb = 0; kb < 4; kb++)
#pragma unroll
                for (int qq = 0; qq < 4; qq++) {
                    uint2 t;
                    t.x = f2tf32(kf[kb * 8 + qq]);
                    t.y = f2tf32(kf[kb * 8 + qq + 4]);
                    *(uint2*)&ks2[kkey * KS + kc0 + kb * 8 + qq * 2] = t;
                }
        }
        {
            const float* vgl = qkv + base + (size_t)(kt * 64 + vr0) * QKV_DIM
                               + 2 * DIM + h * HEAD_DIM + vcs;
            const float* vgh = vgl + (size_t)4 * QKV_DIM;
            float vlo[16], vhi[16];
#pragma unroll
            for (int i = 0; i < 4; i++) {
                float4 a = *(const float4*)(vgl + i * 4);
                float4 c = *(const float4*)(vgh + i * 4);
                vlo[i * 4 + 0] = a.x; vlo[i * 4 + 1] = a.y;
                vlo[i * 4 + 2] = a.z; vlo[i * 4 + 3] = a.w;
                vhi[i * 4 + 0] = c.x; vhi[i * 4 + 1] = c.y;
                vhi[i * 4 + 2] = c.z; vhi[i * 4 + 3] = c.w;
            }
#pragma unroll
            for (int i = 0; i < 16; i++) {
                uint2 t;
                t.x = f2tf32(vlo[i]);
                t.y = f2tf32(vhi[i]);
                *(uint2*)&vp[(vcs + i) * KS + vkb * 8 + vq * 2] = t;
            }
        }
        __syncthreads();

        // ---- S = Q*K^T : kc outer, nc inner -> 16 independent chains ----
        float sc[2][8][4];
#pragma unroll
        for (int nc = 0; nc < 8; nc++)
#pragma unroll
            for (int e = 0; e < 4; e++) { sc[0][nc][e] = 0.f; sc[1][nc][e] = 0.f; }
#pragma unroll
        for (int kc = 0; kc < 8; kc++) {
#pragma unroll
            for (int nc = 0; nc < 8; nc++) {
                const int key = nc * 8 + r0;
                uint2 kk = *(const uint2*)&ks2[key * KS + kc * 8 + q4 * 2];
                mma_tf32(sc[0][nc], qa[0][kc], kk.x, kk.y);
                mma_tf32(sc[1][nc], qa[1][kc], kk.x, kk.y);
            }
        }

#pragma unroll
        for (int mt = 0; mt < 2; mt++) {
            float tA = -1e30f, tB = -1e30f;
#pragma unroll
            for (int nc = 0; nc < 8; nc++) {
                tA = fmaxf(tA, fmaxf(sc[mt][nc][0], sc[mt][nc][1]));
                tB = fmaxf(tB, fmaxf(sc[mt][nc][2], sc[mt][nc][3]));
            }
            tA = fmaxf(tA, __shfl_xor_sync(0xffffffffu, tA, 1));
            tA = fmaxf(tA, __shfl_xor_sync(0xffffffffu, tA, 2));
            tB = fmaxf(tB, __shfl_xor_sync(0xffffffffu, tB, 1));
            tB = fmaxf(tB, __shfl_xor_sync(0xffffffffu, tB, 2));
            const float mnA = fmaxf(mA[mt], tA);
            const float mnB = fmaxf(mB[mt], tB);
            const float cA = ex2(mA[mt] - mnA);
            const float cB = ex2(mB[mt] - mnB);
            mA[mt] = mnA; mB[mt] = mnB;
            lA[mt] *= cA; lB[mt] *= cB;
#pragma unroll
            for (int nc = 0; nc < 8; nc++) {
                o[mt][nc][0] *= cA; o[mt][nc][1] *= cA;
                o[mt][nc][2] *= cB; o[mt][nc][3] *= cB;
                const float p0 = ex2(sc[mt][nc][0] - mnA);
                const float p1 = ex2(sc[mt][nc][1] - mnA);
                const float p2 = ex2(sc[mt][nc][2] - mnB);
                const float p3 = ex2(sc[mt][nc][3] - mnB);
                lA[mt] += p0 + p1; lB[mt] += p2 + p3;
                uint4 stv;
                stv.x = f2tf32(p0); stv.y = f2tf32(p2);
                stv.z = f2tf32(p1); stv.w = f2tf32(p3);
                *(uint4*)&pw[(mt * 8 + r0) * PS + (nc * 8 + 2 * q4) * 2] = stv;
            }
        }
        __syncwarp();

#pragma unroll
        for (int kb = 0; kb < 8; kb++) {
            unsigned af[2][4];
#pragma unroll
            for (int mt = 0; mt < 2; mt++) {
                const unsigned* pr = &pw[(mt * 8 + r0) * PS + (kb * 8 + q4) * 2];
                uint2 a0 = *(const uint2*)pr;
                uint2 a1 = *(const uint2*)(pr + 8);
                af[mt][0] = a0.x; af[mt][1] = a0.y;
                af[mt][2] = a1.x; af[mt][3] = a1.y;
            }
#pragma unroll
            for (int nc = 0; nc < 8; nc++) {
                uint2 vv = *(const uint2*)&vp[(nc * 8 + r0) * KS + kb * 8 + q4 * 2];
                mma_tf32(o[0][nc], af[0], vv.x, vv.y);
                mma_tf32(o[1][nc], af[1], vv.x, vv.y);
            }
        }
        __syncthreads();
    }

#pragma unroll
    for (int mt = 0; mt < 2; mt++) {
        float la = lA[mt], lb = lB[mt];
        la += __shfl_xor_sync(0xffffffffu, la, 1);
        la += __shfl_xor_sync(0xffffffffu, la, 2);
        lb += __shfl_xor_sync(0xffffffffu, lb, 1);
        lb += __shfl_xor_sync(0xffffffffu, lb, 2);
        const float ia = 1.f / la, ib = 1.f / lb;
        const int row = qt * 128 + wid * 32 + mt * 16 + r0;
        float* oA = out + ((size_t)b * SEQ + row) * DIM + h * HEAD_DIM;
        float* oB = oA + (size_t)8 * DIM;
#pragma unroll
        for (int nc = 0; nc < 8; nc++) {
            const int col = nc * 8 + 2 * q4;
            *(float2*)(oA + col) = make_float2(o[mt][nc][0] * ia, o[mt][nc][1] * ia);
            *(float2*)(oB + col) = make_float2(o[mt][nc][2] * ib, o[mt][nc][3] * ib);
        }
    }
}

// ===========================================================================
extern "C" void kernel_launch(void* const* d_in, const int* in_sizes, int n_in,
                              void* d_out, int out_size) {
    const float* x      = (const float*)d_in[0];
    const float* w_qkv  = (const float*)d_in[1];
    const float* b_qkv  = (const float*)d_in[2];
    const float* w_proj = (const float*)d_in[3];
    const float* b_proj = (const float*)d_in[4];
    float* out = (float*)d_out;

    float* qkv = nullptr;
    float* att = nullptr;
    cudaGetSymbolAddress((void**)&qkv, g_qkv);
    cudaGetSymbolAddress((void**)&att, g_att);

    const int M = BATCH * SEQ;                 // 8192
    const int GEMM_SMEM = 2 * G_BUF * 4;       // 58368 B
    const int FA_SMEM = F_WORDS * 4;           // 71680 B

    cudaFuncSetAttribute(gemm_tf32_v5, cudaFuncAttributeMaxDynamicSharedMemorySize,
                         GEMM_SMEM);
    cudaFuncSetAttribute(flash_tf32_v4, cudaFuncAttributeMaxDynamicSharedMemorySize,
                         FA_SMEM);

    {
        dim3 grid(QKV_DIM / 128, M / 128);     // (18, 64)
        gemm_tf32_v5<<<grid, 256, GEMM_SMEM>>>(x, w_qkv, b_qkv, qkv, M, QKV_DIM, DIM);
    }
    {
        dim3 grid(SEQ / 128, HEADS, BATCH);    // (16, 12, 4)
        flash_tf32_v4<<<grid, 128, FA_SMEM>>>(qkv, att);
    }
    {
        dim3 grid(DIM / 128, M / 128);         // (6, 64)
        gemm_tf32_v5<<<grid, 256, GEMM_SMEM>>>(att, w_proj, b_proj, out, M, DIM, DIM);
    }
}